// round 1
// baseline (speedup 1.0000x reference)
#include <cuda_runtime.h>
#include <cuda_bf16.h>
#include <cstdint>

// Problem constants
#define BB 64
#define TT 2048
#define EE 256
#define BT (BB*TT)

// Scratch (device globals; no allocation allowed)
// xg stored time-major: [T+pad][B] float4 (gates i,f,g,o; gates 0,1,3 pre-halved, bias folded)
__device__ float4 g_xg[(TT + 8) * BB];
// raw hidden states, time-major [T][B]
__device__ float  g_hs[TT * BB];

__device__ __forceinline__ float tanha(float x) {
    float y;
    asm("tanh.approx.f32 %0, %1;" : "=f"(y) : "f"(x));
    return y;
}

// ---------------------------------------------------------------------------
// Kernel 1: gate projection. One warp per (b,t). 256 threads = 8 warps/block.
// xg[t][b] = {0.5*(x0+bias0), 0.5*(x1+bias1), x2+bias2, 0.5*(x3+bias3)}
// ---------------------------------------------------------------------------
__global__ __launch_bounds__(256) void gates_kernel(
    const float* __restrict__ data,
    const float* __restrict__ w_ih,
    const float* __restrict__ b_ih,
    const float* __restrict__ b_hh)
{
    __shared__ float ws[4 * EE];
    for (int i = threadIdx.x; i < 4 * EE; i += 256) ws[i] = w_ih[i];
    __syncthreads();

    const int warp = threadIdx.x >> 5;
    const int lane = threadIdx.x & 31;
    const int bt = blockIdx.x * 8 + warp;   // 131072 total, grid = 16384

    const float4* dp = reinterpret_cast<const float4*>(data) + (size_t)bt * (EE / 4);
    float4 d0 = dp[lane];
    float4 d1 = dp[lane + 32];

    const float4* wv = reinterpret_cast<const float4*>(ws);
    float acc[4];
#pragma unroll
    for (int g = 0; g < 4; g++) {
        float4 w0 = wv[g * 64 + lane];
        float4 w1 = wv[g * 64 + lane + 32];
        float s;
        s = d0.x * w0.x;
        s = fmaf(d0.y, w0.y, s);
        s = fmaf(d0.z, w0.z, s);
        s = fmaf(d0.w, w0.w, s);
        s = fmaf(d1.x, w1.x, s);
        s = fmaf(d1.y, w1.y, s);
        s = fmaf(d1.z, w1.z, s);
        s = fmaf(d1.w, w1.w, s);
        acc[g] = s;
    }

#pragma unroll
    for (int off = 16; off > 0; off >>= 1) {
#pragma unroll
        for (int g = 0; g < 4; g++)
            acc[g] += __shfl_xor_sync(0xffffffffu, acc[g], off);
    }

    if (lane == 0) {
        const int b = bt >> 11;      // bt / T
        const int t = bt & (TT - 1); // bt % T
        float bb0 = b_ih[0] + b_hh[0];
        float bb1 = b_ih[1] + b_hh[1];
        float bb2 = b_ih[2] + b_hh[2];
        float bb3 = b_ih[3] + b_hh[3];
        float4 v;
        v.x = 0.5f * (acc[0] + bb0);
        v.y = 0.5f * (acc[1] + bb1);
        v.z =         acc[2] + bb2;
        v.w = 0.5f * (acc[3] + bb3);
        g_xg[t * BB + b] = v;
    }
}

// ---------------------------------------------------------------------------
// Kernel 2: the serial scan. 2 blocks x 32 threads; thread = one batch chain.
// Carry: c, tc=tanh(c_prev_new), wo_k = (scaled) w_k * o_prev.
//   g_k = fma(wo_k, tc, x_k)     (x halved for sigmoid gates)
//   i,f,o = 0.5 + 0.5*tanh(g);  gg = tanh(g2)
//   c = f*c + i*gg; tc = tanh(c); h = o*tc
// Critical path ~48 cyc/step. x prefetched 8 iterations ahead.
// ---------------------------------------------------------------------------
__global__ __launch_bounds__(32) void scan_kernel(const float* __restrict__ w_hh)
{
    const int b = blockIdx.x * 32 + threadIdx.x;   // 0..63

    const float w0h = 0.5f * w_hh[0];
    const float w1h = 0.5f * w_hh[1];
    const float w2f =        w_hh[2];
    const float w3h = 0.5f * w_hh[3];

    const float4* xp = g_xg + b;   // element t is xp[t*BB]

    float4 buf[8];
#pragma unroll
    for (int i = 0; i < 8; i++) buf[i] = xp[i * BB];

    float c = 0.f, tc = 0.f;
    float wo0 = 0.f, wo1 = 0.f, wo2 = 0.f, wo3 = 0.f;

    for (int t = 0; t < TT; t += 8) {
#pragma unroll
        for (int u = 0; u < 8; u++) {
            float4 x = buf[u];
            buf[u] = xp[(t + u + 8) * BB];   // padded array: always in bounds

            float gg0 = fmaf(wo0, tc, x.x);
            float gg1 = fmaf(wo1, tc, x.y);
            float gg2 = fmaf(wo2, tc, x.z);
            float gg3 = fmaf(wo3, tc, x.w);

            float t0 = tanha(gg0);
            float t1 = tanha(gg1);
            float tg = tanha(gg2);
            float t3 = tanha(gg3);

            float i = fmaf(0.5f, t0, 0.5f);
            float f = fmaf(0.5f, t1, 0.5f);
            float o = fmaf(0.5f, t3, 0.5f);

            c  = fmaf(f, c, i * tg);
            tc = tanha(c);

            wo0 = w0h * o;
            wo1 = w1h * o;
            wo2 = w2f * o;
            wo3 = w3h * o;

            g_hs[(t + u) * BB + b] = o * tc;
        }
    }
}

// ---------------------------------------------------------------------------
// Kernel 3: transpose [T][B] -> [B][T] with sigmoid + mask.
// masked positions: where() puts 0 before sigmoid -> output 0.5
// block (32,8), tile 32x32, grid (T/32, B/32)
// ---------------------------------------------------------------------------
__global__ __launch_bounds__(256) void out_kernel(
    const int* __restrict__ seq, float* __restrict__ out)
{
    __shared__ float tile[32][33];
    const int tx = threadIdx.x, ty = threadIdx.y;
    const int t0 = blockIdx.x * 32, b0 = blockIdx.y * 32;

#pragma unroll
    for (int j = 0; j < 4; j++) {
        int t = t0 + ty + j * 8;
        tile[ty + j * 8][tx] = g_hs[t * BB + b0 + tx];
    }
    __syncthreads();

#pragma unroll
    for (int j = 0; j < 4; j++) {
        int bb = b0 + ty + j * 8;
        int t  = t0 + tx;
        float h = tile[tx][ty + j * 8];
        float v = (t < seq[bb]) ? __fdividef(1.f, 1.f + __expf(-h)) : 0.5f;
        out[(size_t)bb * TT + t] = v;
    }
}

// Tail: if harness concatenates the tuple (out, seq_length), append seq as float
__global__ void tail_kernel(const int* __restrict__ seq, float* __restrict__ out, int n)
{
    int i = threadIdx.x;
    if (i < n) out[BT + i] = (float)seq[i];
}

extern "C" void kernel_launch(void* const* d_in, const int* in_sizes, int n_in,
                              void* d_out, int out_size)
{
    const float* data = (const float*)d_in[0];
    const int*   seq  = (const int*)  d_in[1];
    const float* w_ih = (const float*)d_in[2];
    const float* w_hh = (const float*)d_in[3];
    const float* b_ih = (const float*)d_in[4];
    const float* b_hh = (const float*)d_in[5];
    float* out = (float*)d_out;

    gates_kernel<<<BT / 8, 256>>>(data, w_ih, b_ih, b_hh);
    scan_kernel<<<2, 32>>>(w_hh);
    out_kernel<<<dim3(TT / 32, BB / 32), dim3(32, 8)>>>(seq, out);

    int tail = out_size - BT;
    if (tail > 0) {
        tail_kernel<<<1, 64>>>(seq, out, tail);
    }
}

// round 2
// speedup vs baseline: 1.4067x; 1.4067x over previous
#include <cuda_runtime.h>
#include <cuda_bf16.h>
#include <cstdint>

#define BB 64
#define TT 2048
#define EE 256
#define BT (BB*TT)
#define CHUNK 32
#define NCHUNK (TT/CHUNK)              // 64
#define TASKS_PER_CHUNK (CHUNK*BB)     // 2048
#define NBLK 148
#define GATE_BLOCKS (NBLK-1)           // 147
#define TPB 512

// xg time-major [T+pad][B] float4: gates (i,f,g,o); sigmoid gates pre-halved, bias folded
__device__ float4 g_xg[(TT + 16) * BB];
// per-chunk completion counters; zero-init at load, reset by scan block each launch
__device__ int g_cnt[NCHUNK];

__device__ __forceinline__ float tanha(float x) {
    float y;
    asm("tanh.approx.f32 %0, %1;" : "=f"(y) : "f"(x));
    return y;
}

__global__ __launch_bounds__(TPB, 1) void fused_kernel(
    const float* __restrict__ data,
    const int*   __restrict__ seq,
    const float* __restrict__ w_ih,
    const float* __restrict__ w_hh,
    const float* __restrict__ b_ih,
    const float* __restrict__ b_hh,
    float* __restrict__ out,
    int tail)
{
    const int tid  = threadIdx.x;
    const int warp = tid >> 5;
    const int lane = tid & 31;

    if (blockIdx.x != 0) {
        // ================= GATE BLOCKS =================
        const int kb = blockIdx.x - 1;                       // 0..146
        const int lo = (kb * TASKS_PER_CHUNK) / GATE_BLOCKS;
        const int hi = ((kb + 1) * TASKS_PER_CHUNK) / GATE_BLOCKS;
        const int nt = hi - lo;                              // 13 or 14
        const bool active = (warp < nt);

        // weights in registers: 8 float4 per thread
        const float4* wv = reinterpret_cast<const float4*>(w_ih);
        float4 wr[8];
#pragma unroll
        for (int g = 0; g < 4; g++) {
            wr[2*g]   = __ldg(wv + g*64 + lane);
            wr[2*g+1] = __ldg(wv + g*64 + 32 + lane);
        }
        const float bb0 = __ldg(b_ih+0) + __ldg(b_hh+0);
        const float bb1 = __ldg(b_ih+1) + __ldg(b_hh+1);
        const float bb2 = __ldg(b_ih+2) + __ldg(b_hh+2);
        const float bb3 = __ldg(b_ih+3) + __ldg(b_hh+3);

        const int s    = lo + warp;           // task slot within each chunk
        const int bidx = s & 63;
        const int trow = s >> 6;              // 0..31

        const float4* dp = reinterpret_cast<const float4*>(data)
                         + ((size_t)bidx * TT + trow) * (EE/4);
        float4 d0, d1;
        if (active) { d0 = __ldcs(dp + lane); d1 = __ldcs(dp + 32 + lane); }

        for (int c = 0; c < NCHUNK; c++) {
            const float4* dpn = dp + 32 * (EE/4);
            float4 n0, n1;
            if (active && c < NCHUNK-1) { n0 = __ldcs(dpn + lane); n1 = __ldcs(dpn + 32 + lane); }

            if (active) {
                float a0, a1, a2, a3;
                {
                    float4 w0 = wr[0], w1 = wr[1];
                    a0 = d0.x*w0.x; a0 = fmaf(d0.y,w0.y,a0); a0 = fmaf(d0.z,w0.z,a0); a0 = fmaf(d0.w,w0.w,a0);
                    a0 = fmaf(d1.x,w1.x,a0); a0 = fmaf(d1.y,w1.y,a0); a0 = fmaf(d1.z,w1.z,a0); a0 = fmaf(d1.w,w1.w,a0);
                }
                {
                    float4 w0 = wr[2], w1 = wr[3];
                    a1 = d0.x*w0.x; a1 = fmaf(d0.y,w0.y,a1); a1 = fmaf(d0.z,w0.z,a1); a1 = fmaf(d0.w,w0.w,a1);
                    a1 = fmaf(d1.x,w1.x,a1); a1 = fmaf(d1.y,w1.y,a1); a1 = fmaf(d1.z,w1.z,a1); a1 = fmaf(d1.w,w1.w,a1);
                }
                {
                    float4 w0 = wr[4], w1 = wr[5];
                    a2 = d0.x*w0.x; a2 = fmaf(d0.y,w0.y,a2); a2 = fmaf(d0.z,w0.z,a2); a2 = fmaf(d0.w,w0.w,a2);
                    a2 = fmaf(d1.x,w1.x,a2); a2 = fmaf(d1.y,w1.y,a2); a2 = fmaf(d1.z,w1.z,a2); a2 = fmaf(d1.w,w1.w,a2);
                }
                {
                    float4 w0 = wr[6], w1 = wr[7];
                    a3 = d0.x*w0.x; a3 = fmaf(d0.y,w0.y,a3); a3 = fmaf(d0.z,w0.z,a3); a3 = fmaf(d0.w,w0.w,a3);
                    a3 = fmaf(d1.x,w1.x,a3); a3 = fmaf(d1.y,w1.y,a3); a3 = fmaf(d1.z,w1.z,a3); a3 = fmaf(d1.w,w1.w,a3);
                }
#pragma unroll
                for (int off = 16; off > 0; off >>= 1) {
                    a0 += __shfl_xor_sync(0xffffffffu, a0, off);
                    a1 += __shfl_xor_sync(0xffffffffu, a1, off);
                    a2 += __shfl_xor_sync(0xffffffffu, a2, off);
                    a3 += __shfl_xor_sync(0xffffffffu, a3, off);
                }
                if (lane == 0) {
                    const int t = c * CHUNK + trow;
                    float4 v;
                    v.x = 0.5f * (a0 + bb0);
                    v.y = 0.5f * (a1 + bb1);
                    v.z =         a2 + bb2;
                    v.w = 0.5f * (a3 + bb3);
                    g_xg[t * BB + bidx] = v;
                }
            }
            __threadfence();
            __syncthreads();
            if (tid == 0) atomicAdd(&g_cnt[c], nt);

            d0 = n0; d1 = n1; dp = dpn;
        }
        return;
    }

    // ================= SCAN BLOCK (block 0) =================
    if (warp >= 2) return;   // two warps = 64 chains

    const int b  = warp * 32 + lane;
    const float w0h = 0.5f * __ldg(w_hh+0);
    const float w1h = 0.5f * __ldg(w_hh+1);
    const float w2f =        __ldg(w_hh+2);
    const float w3h = 0.5f * __ldg(w_hh+3);
    const int   sb  = __ldg(seq + b);

    const float4* xp = g_xg + b;          // element t at xp[t*BB]
    float4* orow = reinterpret_cast<float4*>(out + (size_t)b * TT);

    // wait for chunks 0 and 1 (prefetch reach)
    if (warp == 0) {
        while (*(volatile const int*)(g_cnt + 0) < TASKS_PER_CHUNK) { }
        while (*(volatile const int*)(g_cnt + 1) < TASKS_PER_CHUNK) { }
        __threadfence();
    }
    asm volatile("bar.sync 1, 64;" ::: "memory");

    float4 buf[8];
#pragma unroll
    for (int i = 0; i < 8; i++) buf[i] = __ldcg(xp + i * BB);

    float c = 0.f, tc = 0.f;
    float wo0 = 0.f, wo1 = 0.f, wo2 = 0.f, wo3 = 0.f;
    float hb0, hb1, hb2;

    for (int ch = 0; ch < NCHUNK; ch++) {
#pragma unroll
        for (int u = 0; u < CHUNK; u++) {
            const int t = ch * CHUNK + u;
            float4 x = buf[t & 7];
            buf[t & 7] = __ldcg(xp + (t + 8) * BB);   // padded: always in bounds

            float g0 = fmaf(wo0, tc, x.x);
            float g1 = fmaf(wo1, tc, x.y);
            float g2 = fmaf(wo2, tc, x.z);
            float g3 = fmaf(wo3, tc, x.w);

            float t0 = tanha(g0);
            float t1 = tanha(g1);
            float tg = tanha(g2);
            float t3 = tanha(g3);

            float i = fmaf(0.5f, t0, 0.5f);
            float f = fmaf(0.5f, t1, 0.5f);
            float o = fmaf(0.5f, t3, 0.5f);

            c  = fmaf(f, c, i * tg);
            tc = tanha(c);

            wo0 = w0h * o; wo1 = w1h * o; wo2 = w2f * o; wo3 = w3h * o;

            float h = o * tc;
            float v = (t < sb) ? fmaf(0.5f, tanha(0.5f * h), 0.5f) : 0.5f;
            int ph = t & 3;
            if (ph == 0) hb0 = v;
            else if (ph == 1) hb1 = v;
            else if (ph == 2) hb2 = v;
            else orow[t >> 2] = make_float4(hb0, hb1, hb2, v);
        }
        // ensure chunk ch+2 is ready (covers prefetch during chunk ch+1)
        if (ch + 2 < NCHUNK) {
            if (warp == 0) {
                while (*(volatile const int*)(g_cnt + ch + 2) < TASKS_PER_CHUNK) { }
                __threadfence();
            }
            asm volatile("bar.sync 1, 64;" ::: "memory");
        }
    }

    // reset counters for the next graph replay (all producers finished:
    // cnt[63]==2048 was observed, which is every gate block's final atomic)
    if (warp == 0) {
        g_cnt[lane] = 0;
        g_cnt[lane + 32] = 0;
    }
    // tail: append seq_length as float if the output buffer carries the tuple
    if (b < tail) out[BT + b] = (float)sb;
}

extern "C" void kernel_launch(void* const* d_in, const int* in_sizes, int n_in,
                              void* d_out, int out_size)
{
    const float* data = (const float*)d_in[0];
    const int*   seq  = (const int*)  d_in[1];
    const float* w_ih = (const float*)d_in[2];
    const float* w_hh = (const float*)d_in[3];
    const float* b_ih = (const float*)d_in[4];
    const float* b_hh = (const float*)d_in[5];
    float* out = (float*)d_out;

    int tail = out_size - BT;
    if (tail < 0) tail = 0;
    if (tail > BB) tail = BB;

    fused_kernel<<<NBLK, TPB>>>(data, seq, w_ih, w_hh, b_ih, b_hh, out, tail);
}

// round 3
// speedup vs baseline: 1.4967x; 1.0639x over previous
#include <cuda_runtime.h>
#include <cuda_bf16.h>
#include <cstdint>

#define BB 64
#define TT 2048
#define EE 256
#define BT (BB*TT)
#define CHUNK 32
#define NCHUNK (TT/CHUNK)              // 64
#define GATE_BLOCKS 128
#define TPB 512
#define FULLCNT 2048                   // 128 blocks * 16 warps per chunk

// xg time-major [T+pad][B] float4 (gates i,f,g,o; sigmoid gates pre-halved, bias folded)
__device__ float4 g_xg[(TT + 16) * BB];
// raw hidden states, time-major [T][B]
__device__ float  g_hs[TT * BB];
// producer->scan per-chunk counters (reset by scan at end of each launch)
__device__ int g_cnt[NCHUNK];
// scan->epilogue flags, one per (chunk, b-half), padded to 32B (reset by its sole consumer)
__device__ int g_sdone[NCHUNK * 2 * 8];

__device__ __forceinline__ float tanha(float x) {
    float y; asm("tanh.approx.f32 %0, %1;" : "=f"(y) : "f"(x)); return y;
}
__device__ __forceinline__ int acq_ld(const int* p) {
    int v; asm volatile("ld.acquire.gpu.global.b32 %0, [%1];" : "=r"(v) : "l"(p) : "memory"); return v;
}
__device__ __forceinline__ void rel_add(int* p, int v) {
    asm volatile("red.release.gpu.global.add.s32 [%0], %1;" :: "l"(p), "r"(v) : "memory");
}
__device__ __forceinline__ float sigf(float h) {
    return fmaf(0.5f, tanha(0.5f * h), 0.5f);
}

__global__ __launch_bounds__(TPB, 1) void fused_kernel(
    const float* __restrict__ data,
    const int*   __restrict__ seq,
    const float* __restrict__ w_ih,
    const float* __restrict__ w_hh,
    const float* __restrict__ b_ih,
    const float* __restrict__ b_hh,
    float* __restrict__ out,
    int tail)
{
    const int tid  = threadIdx.x;
    const int warp = tid >> 5;
    const int lane = tid & 31;

    if (blockIdx.x == 0) {
        // ================= SCAN BLOCK =================
        if (warp >= 2) return;
        const int b  = warp * 32 + lane;
        const float w0h = 0.5f * __ldg(w_hh+0);
        const float w1h = 0.5f * __ldg(w_hh+1);
        const float w2f =        __ldg(w_hh+2);
        const float w3h = 0.5f * __ldg(w_hh+3);
        const int   sb  = __ldg(seq + b);

        const float4* xp = g_xg + b;         // element t at xp[t*BB]
        float* hp = g_hs + b;

        int ready = 0;
        // need chunks 0 and 1 before prefetching
        while (ready < 2) {
            if (acq_ld(g_cnt + ready) == FULLCNT) ready++;
        }

        float4 buf[8];
#pragma unroll
        for (int i = 0; i < 8; i++) buf[i] = __ldcg(xp + i * BB);

        float c = 0.f, tc = 0.f;
        float wo0 = 0.f, wo1 = 0.f, wo2 = 0.f, wo3 = 0.f;

        for (int ch = 0; ch < NCHUNK; ch++) {
            // ensure chunks [0, ch+2) done (prefetch reaches into ch+1)
            const int need = (ch + 2 < NCHUNK) ? (ch + 2) : NCHUNK;
            while (ready < need) {
                int far = ready + 6; if (far > NCHUNK-1) far = NCHUNK-1;
                if (acq_ld(g_cnt + far) == FULLCNT)        ready = far + 1;
                else if (acq_ld(g_cnt + ready) == FULLCNT) ready++;
            }
#pragma unroll
            for (int u = 0; u < CHUNK; u++) {
                const int t = ch * CHUNK + u;
                float4 x = buf[u & 7];
                buf[u & 7] = __ldcg(xp + (t + 8) * BB);   // padded: always in bounds

                float g0 = fmaf(wo0, tc, x.x);
                float g1 = fmaf(wo1, tc, x.y);
                float g2 = fmaf(wo2, tc, x.z);
                float g3 = fmaf(wo3, tc, x.w);

                float t0 = tanha(g0);
                float t1 = tanha(g1);
                float tg = tanha(g2);
                float t3 = tanha(g3);

                float i = fmaf(0.5f, t0, 0.5f);
                float f = fmaf(0.5f, t1, 0.5f);
                float o = fmaf(0.5f, t3, 0.5f);

                c  = fmaf(f, c, i * tg);
                tc = tanha(c);

                wo0 = w0h * o; wo1 = w1h * o; wo2 = w2f * o; wo3 = w3h * o;

                hp[t * BB] = o * tc;          // raw h; epilogue applies sigmoid+mask
            }
            __syncwarp();
            if (lane == 0) rel_add(&g_sdone[(ch * 2 + warp) * 8], 1);
        }

        // reset producer counters for next graph replay (all observed full above)
        g_cnt[b] = 0;
        // tail: append seq_length as float if output carries the tuple
        if (b < tail) out[BT + b] = (float)sb;
        return;
    }

    // ================= GATE + EPILOGUE BLOCKS (1..128) =================
    const int kb = blockIdx.x - 1;            // 0..127
    const int s  = kb * 16 + warp;            // 0..2047: task slot within each chunk
    const int bidx = s & 63;
    const int trow = s >> 6;                  // 0..31

    // weights in registers
    const float4* wv = reinterpret_cast<const float4*>(w_ih);
    float4 wr[8];
#pragma unroll
    for (int g = 0; g < 4; g++) {
        wr[2*g]   = __ldg(wv + g*64 + lane);
        wr[2*g+1] = __ldg(wv + g*64 + 32 + lane);
    }
    const float bb0 = __ldg(b_ih+0) + __ldg(b_hh+0);
    const float bb1 = __ldg(b_ih+1) + __ldg(b_hh+1);
    const float bb2 = __ldg(b_ih+2) + __ldg(b_hh+2);
    const float bb3 = __ldg(b_ih+3) + __ldg(b_hh+3);

    const float4* dpb = reinterpret_cast<const float4*>(data)
                      + ((size_t)bidx * TT + trow) * (EE/4);
    const int cstride = CHUNK * (EE/4);       // float4 stride per chunk (32 rows)

    // depth-4 chunk prefetch pipeline
    float4 A0[4], A1[4];
#pragma unroll
    for (int p = 0; p < 4; p++) {
        A0[p] = __ldcs(dpb + p * cstride + lane);
        A1[p] = __ldcs(dpb + p * cstride + 32 + lane);
    }

#pragma unroll 4
    for (int c = 0; c < NCHUNK; c++) {
        const int slot = c & 3;
        float4 d0 = A0[slot], d1 = A1[slot];
        if (c + 4 < NCHUNK) {
            A0[slot] = __ldcs(dpb + (c + 4) * cstride + lane);
            A1[slot] = __ldcs(dpb + (c + 4) * cstride + 32 + lane);
        }

        float a0, a1, a2, a3;
        {
            float4 w0 = wr[0], w1 = wr[1];
            a0 = d0.x*w0.x; a0 = fmaf(d0.y,w0.y,a0); a0 = fmaf(d0.z,w0.z,a0); a0 = fmaf(d0.w,w0.w,a0);
            a0 = fmaf(d1.x,w1.x,a0); a0 = fmaf(d1.y,w1.y,a0); a0 = fmaf(d1.z,w1.z,a0); a0 = fmaf(d1.w,w1.w,a0);
        }
        {
            float4 w0 = wr[2], w1 = wr[3];
            a1 = d0.x*w0.x; a1 = fmaf(d0.y,w0.y,a1); a1 = fmaf(d0.z,w0.z,a1); a1 = fmaf(d0.w,w0.w,a1);
            a1 = fmaf(d1.x,w1.x,a1); a1 = fmaf(d1.y,w1.y,a1); a1 = fmaf(d1.z,w1.z,a1); a1 = fmaf(d1.w,w1.w,a1);
        }
        {
            float4 w0 = wr[4], w1 = wr[5];
            a2 = d0.x*w0.x; a2 = fmaf(d0.y,w0.y,a2); a2 = fmaf(d0.z,w0.z,a2); a2 = fmaf(d0.w,w0.w,a2);
            a2 = fmaf(d1.x,w1.x,a2); a2 = fmaf(d1.y,w1.y,a2); a2 = fmaf(d1.z,w1.z,a2); a2 = fmaf(d1.w,w1.w,a2);
        }
        {
            float4 w0 = wr[6], w1 = wr[7];
            a3 = d0.x*w0.x; a3 = fmaf(d0.y,w0.y,a3); a3 = fmaf(d0.z,w0.z,a3); a3 = fmaf(d0.w,w0.w,a3);
            a3 = fmaf(d1.x,w1.x,a3); a3 = fmaf(d1.y,w1.y,a3); a3 = fmaf(d1.z,w1.z,a3); a3 = fmaf(d1.w,w1.w,a3);
        }
#pragma unroll
        for (int off = 16; off > 0; off >>= 1) {
            a0 += __shfl_xor_sync(0xffffffffu, a0, off);
            a1 += __shfl_xor_sync(0xffffffffu, a1, off);
            a2 += __shfl_xor_sync(0xffffffffu, a2, off);
            a3 += __shfl_xor_sync(0xffffffffu, a3, off);
        }
        if (lane == 0) {
            const int t = c * CHUNK + trow;
            float4 v;
            v.x = 0.5f * (a0 + bb0);
            v.y = 0.5f * (a1 + bb1);
            v.z =         a2 + bb2;
            v.w = 0.5f * (a3 + bb3);
            g_xg[t * BB + bidx] = v;
        }
        __syncthreads();                       // cta-order all warps' xg stores
        if (tid == 0) rel_add(&g_cnt[c], 16);  // cumulative release
    }

    // -------- epilogue: one 32x32 (t,b) tile per block --------
    const int tch = kb >> 1;                   // which scan chunk (0..63)
    const int bh  = kb & 1;                    // which b-half (warp of scan block)
    const int slot = (tch * 2 + bh) * 8;

    if (tid == 0) {
        unsigned ns = 256;
        while (acq_ld(&g_sdone[slot]) == 0) {
            __nanosleep(ns);
            if (ns < 4096) ns += ns;
        }
        g_sdone[slot] = 0;                     // sole consumer resets for next replay
    }
    __syncthreads();                           // broadcast acquire to whole block

    __shared__ float tile[32][33];
    const int r = tid >> 5;                    // 0..15
    const int j = tid & 31;
    const int t0 = tch * 32, b0 = bh * 32;

    tile[r][j]      = __ldcg(&g_hs[(t0 + r)      * BB + b0 + j]);
    tile[r + 16][j] = __ldcg(&g_hs[(t0 + r + 16) * BB + b0 + j]);
    __syncthreads();

    {
        const int sb1 = __ldg(seq + b0 + r);
        float h = tile[j][r];
        out[(size_t)(b0 + r) * TT + t0 + j] = (t0 + j < sb1) ? sigf(h) : 0.5f;
    }
    {
        const int sb2 = __ldg(seq + b0 + r + 16);
        float h = tile[j][r + 16];
        out[(size_t)(b0 + r + 16) * TT + t0 + j] = (t0 + j < sb2) ? sigf(h) : 0.5f;
    }
}

extern "C" void kernel_launch(void* const* d_in, const int* in_sizes, int n_in,
                              void* d_out, int out_size)
{
    const float* data = (const float*)d_in[0];
    const int*   seq  = (const int*)  d_in[1];
    const float* w_ih = (const float*)d_in[2];
    const float* w_hh = (const float*)d_in[3];
    const float* b_ih = (const float*)d_in[4];
    const float* b_hh = (const float*)d_in[5];
    float* out = (float*)d_out;

    int tail = out_size - BT;
    if (tail < 0) tail = 0;
    if (tail > BB) tail = BB;

    fused_kernel<<<1 + GATE_BLOCKS, TPB>>>(data, seq, w_ih, w_hh, b_ih, b_hh, out, tail);
}

// round 4
// speedup vs baseline: 1.7539x; 1.1718x over previous
#include <cuda_runtime.h>
#include <cuda_bf16.h>
#include <cstdint>

#define BB 64
#define TT 2048
#define EE 256
#define BT (BB*TT)
#define CHUNK 32
#define NCHUNK (TT/CHUNK)              // 64
#define NSCAN 8                        // scan blocks, 8 chains each
#define GATE_BLOCKS 128
#define TPB 512
#define FULLCNT 2048                   // 128 blocks * 16 warps per chunk

// xg time-major [T+pad][B] float4 (gates i,f,g,o; sigmoid gates pre-halved, bias folded)
__device__ float4 g_xg[(TT + 16) * BB];
// producer->scan per-chunk counters
__device__ int g_cnt[NCHUNK];
// scan completion rendezvous (last finisher resets g_cnt)
__device__ int g_done;

__device__ __forceinline__ float tanha(float x) {
    float y; asm("tanh.approx.f32 %0, %1;" : "=f"(y) : "f"(x)); return y;
}
__device__ __forceinline__ int acq_ld(const int* p) {
    int v; asm volatile("ld.acquire.gpu.global.b32 %0, [%1];" : "=r"(v) : "l"(p) : "memory"); return v;
}
__device__ __forceinline__ void rel_add(int* p, int v) {
    asm volatile("red.release.gpu.global.add.s32 [%0], %1;" :: "l"(p), "r"(v) : "memory");
}

__global__ __launch_bounds__(TPB, 1) void fused_kernel(
    const float* __restrict__ data,
    const int*   __restrict__ seq,
    const float* __restrict__ w_ih,
    const float* __restrict__ w_hh,
    const float* __restrict__ b_ih,
    const float* __restrict__ b_hh,
    float* __restrict__ out,
    int tail)
{
    const int tid  = threadIdx.x;
    const int warp = tid >> 5;
    const int lane = tid & 31;

    if (blockIdx.x < NSCAN) {
        // ================= SCAN BLOCKS (8 chains per block, lanes 0-7) =================
        if (tid >= 8) return;
        const int b  = blockIdx.x * 8 + tid;
        const float w0h = 0.5f * __ldg(w_hh+0);
        const float w1h = 0.5f * __ldg(w_hh+1);
        const float w2f =        __ldg(w_hh+2);
        const float w3h = 0.5f * __ldg(w_hh+3);
        const int   sb  = __ldg(seq + b);

        const float4* xp = g_xg + b;          // element t at xp[t*BB]
        float4* orow = reinterpret_cast<float4*>(out + (size_t)b * TT);

        int ready = 0;
        while (ready < 2) {
            if (acq_ld(g_cnt + ready) == FULLCNT) ready++;
        }

        float4 buf[8];
#pragma unroll
        for (int i = 0; i < 8; i++) buf[i] = __ldcg(xp + i * BB);

        float half_c = 0.f, tc = 0.f;
        float wo0 = 0.f, wo1 = 0.f, wo2 = 0.f, wo3 = 0.f;
        float hb0, hb1, hb2;

        for (int ch = 0; ch < NCHUNK; ch++) {
            const int need = (ch + 2 < NCHUNK) ? (ch + 2) : NCHUNK;
            while (ready < need) {
                int far = ready + 6; if (far > NCHUNK-1) far = NCHUNK-1;
                if (acq_ld(g_cnt + far) == FULLCNT)        ready = far + 1;
                else if (acq_ld(g_cnt + ready) == FULLCNT) ready++;
            }
#pragma unroll
            for (int u = 0; u < CHUNK; u++) {
                const int t = ch * CHUNK + u;
                float4 x = buf[u & 7];
                buf[u & 7] = __ldcg(xp + (t + 8) * BB);   // padded: always in bounds

                // gates (sigmoid gates pre-halved)
                float g1 = fmaf(wo1, tc, x.y);   // f gate first: it's on the c-chain
                float g2 = fmaf(wo2, tc, x.z);
                float g0 = fmaf(wo0, tc, x.x);
                float g3 = fmaf(wo3, tc, x.w);

                float t1 = tanha(g1);
                float tg = tanha(g2);
                float t0 = tanha(g0);
                float t3 = tanha(g3);

                // c = f*c_prev + i*gg  with f=0.5(1+t1), i=0.5(1+t0)
                float r   = fmaf(t1, half_c, half_c);   // f * c_prev
                float tgh = 0.5f * tg;
                float q   = fmaf(t0, tgh, tgh);          // i * gg
                float c   = r + q;
                half_c    = 0.5f * c;                     // off-chain for next step
                tc        = tanha(c);

                float o = fmaf(0.5f, t3, 0.5f);
                wo0 = w0h * o; wo1 = w1h * o; wo2 = w2f * o; wo3 = w3h * o;

                float h = o * tc;
                float v = (t < sb) ? fmaf(0.5f, tanha(0.5f * h), 0.5f) : 0.5f;
                int ph = t & 3;
                if (ph == 0) hb0 = v;
                else if (ph == 1) hb1 = v;
                else if (ph == 2) hb2 = v;
                else orow[t >> 2] = make_float4(hb0, hb1, hb2, v);
            }
        }

        // tail: append seq_length as float if output carries the tuple
        if (b < tail) out[BT + b] = (float)sb;

        // last scan block to finish resets counters for the next graph replay
        __syncwarp(0xFFu);
        if (tid == 0) {
            if (atomicAdd(&g_done, 1) == NSCAN - 1) {
#pragma unroll
                for (int i = 0; i < NCHUNK; i++) g_cnt[i] = 0;
                g_done = 0;
            }
        }
        return;
    }

    // ================= GATE BLOCKS (NSCAN .. NSCAN+127) =================
    const int kb = blockIdx.x - NSCAN;        // 0..127
    const int s  = kb * 16 + warp;            // 0..2047: task slot within each chunk
    const int bidx = s & 63;
    const int trow = s >> 6;                  // 0..31

    const float4* wv = reinterpret_cast<const float4*>(w_ih);
    float4 wr[8];
#pragma unroll
    for (int g = 0; g < 4; g++) {
        wr[2*g]   = __ldg(wv + g*64 + lane);
        wr[2*g+1] = __ldg(wv + g*64 + 32 + lane);
    }
    const float bb0 = __ldg(b_ih+0) + __ldg(b_hh+0);
    const float bb1 = __ldg(b_ih+1) + __ldg(b_hh+1);
    const float bb2 = __ldg(b_ih+2) + __ldg(b_hh+2);
    const float bb3 = __ldg(b_ih+3) + __ldg(b_hh+3);

    const float4* dpb = reinterpret_cast<const float4*>(data)
                      + ((size_t)bidx * TT + trow) * (EE/4);
    const int cstride = CHUNK * (EE/4);       // float4 stride per chunk (32 rows)

    // depth-4 chunk prefetch pipeline
    float4 A0[4], A1[4];
#pragma unroll
    for (int p = 0; p < 4; p++) {
        A0[p] = __ldcs(dpb + p * cstride + lane);
        A1[p] = __ldcs(dpb + p * cstride + 32 + lane);
    }

#pragma unroll 4
    for (int c = 0; c < NCHUNK; c++) {
        const int slot = c & 3;
        float4 d0 = A0[slot], d1 = A1[slot];
        if (c + 4 < NCHUNK) {
            A0[slot] = __ldcs(dpb + (c + 4) * cstride + lane);
            A1[slot] = __ldcs(dpb + (c + 4) * cstride + 32 + lane);
        }

        float a0, a1, a2, a3;
        {
            float4 w0 = wr[0], w1 = wr[1];
            a0 = d0.x*w0.x; a0 = fmaf(d0.y,w0.y,a0); a0 = fmaf(d0.z,w0.z,a0); a0 = fmaf(d0.w,w0.w,a0);
            a0 = fmaf(d1.x,w1.x,a0); a0 = fmaf(d1.y,w1.y,a0); a0 = fmaf(d1.z,w1.z,a0); a0 = fmaf(d1.w,w1.w,a0);
        }
        {
            float4 w0 = wr[2], w1 = wr[3];
            a1 = d0.x*w0.x; a1 = fmaf(d0.y,w0.y,a1); a1 = fmaf(d0.z,w0.z,a1); a1 = fmaf(d0.w,w0.w,a1);
            a1 = fmaf(d1.x,w1.x,a1); a1 = fmaf(d1.y,w1.y,a1); a1 = fmaf(d1.z,w1.z,a1); a1 = fmaf(d1.w,w1.w,a1);
        }
        {
            float4 w0 = wr[4], w1 = wr[5];
            a2 = d0.x*w0.x; a2 = fmaf(d0.y,w0.y,a2); a2 = fmaf(d0.z,w0.z,a2); a2 = fmaf(d0.w,w0.w,a2);
            a2 = fmaf(d1.x,w1.x,a2); a2 = fmaf(d1.y,w1.y,a2); a2 = fmaf(d1.z,w1.z,a2); a2 = fmaf(d1.w,w1.w,a2);
        }
        {
            float4 w0 = wr[6], w1 = wr[7];
            a3 = d0.x*w0.x; a3 = fmaf(d0.y,w0.y,a3); a3 = fmaf(d0.z,w0.z,a3); a3 = fmaf(d0.w,w0.w,a3);
            a3 = fmaf(d1.x,w1.x,a3); a3 = fmaf(d1.y,w1.y,a3); a3 = fmaf(d1.z,w1.z,a3); a3 = fmaf(d1.w,w1.w,a3);
        }
#pragma unroll
        for (int off = 16; off > 0; off >>= 1) {
            a0 += __shfl_xor_sync(0xffffffffu, a0, off);
            a1 += __shfl_xor_sync(0xffffffffu, a1, off);
            a2 += __shfl_xor_sync(0xffffffffu, a2, off);
            a3 += __shfl_xor_sync(0xffffffffu, a3, off);
        }
        if (lane == 0) {
            const int t = c * CHUNK + trow;
            float4 v;
            v.x = 0.5f * (a0 + bb0);
            v.y = 0.5f * (a1 + bb1);
            v.z =         a2 + bb2;
            v.w = 0.5f * (a3 + bb3);
            g_xg[t * BB + bidx] = v;
        }
        __syncthreads();                       // cta-order all warps' xg stores
        if (tid == 0) rel_add(&g_cnt[c], 16);  // cumulative release
    }
}

extern "C" void kernel_launch(void* const* d_in, const int* in_sizes, int n_in,
                              void* d_out, int out_size)
{
    const float* data = (const float*)d_in[0];
    const int*   seq  = (const int*)  d_in[1];
    const float* w_ih = (const float*)d_in[2];
    const float* w_hh = (const float*)d_in[3];
    const float* b_ih = (const float*)d_in[4];
    const float* b_hh = (const float*)d_in[5];
    float* out = (float*)d_out;

    int tail = out_size - BT;
    if (tail < 0) tail = 0;
    if (tail > BB) tail = BB;

    fused_kernel<<<NSCAN + GATE_BLOCKS, TPB>>>(data, seq, w_ih, w_hh, b_ih, b_hh, out, tail);
}